// round 13
// baseline (speedup 1.0000x reference)
// QLSTM: quantum-gate LSTM, T=2048, B=256, D=128, H=NQ=4.
//
// Kernel 1 (qlstm_gemm): pre[t,b,16] = x[t,b,:]@W_g[:128,:] + b_g + theta_g
//   v2: crossbar-balanced blocking. 1 warp per 128-row tile; lane owns
//   8 rows x 8 cols -> W LDS amortized 8x, x reused over 8 cols
//   (0.5 float/fma2 = exactly the 128 B/cyc smem crossbar). x staged in
//   4 k-chunks of 32 cols with an XOR-16 column swizzle so the 16-row
//   vertical LDS.32 pattern is bank-conflict-free.
//
// Kernel 2 (qlstm_scan): sequence-parallel recurrence. f = sigmoid(p),
//   p in [-1,1] -> contraction <= ~0.75/step; BURN=256 was bit-exact, so
//   BURN=128 (residual <= 1.4e-6 even at rho=0.9). CHUNK=64: serial wall
//   = 192 steps. Per-step: quad layout + 4x4 butterfly transpose, 4-deep
//   register prefetch ring, MUFU.TANH gates, ex2+rcp tanh(c).

#include <cuda_runtime.h>
#include <cstdint>

#define TT 2048
#define BB 256
#define DD 128
#define ROWS (TT * BB)   // 524288
#define CHUNK 64
#define NCHUNK (TT / CHUNK)   // 32
#define BURN 128

// scratch: pre-activations [T][B][16] + 4 timesteps padding (ring overrun)
__device__ __align__(128) float g_pre[(TT + 4) * BB * 16];

// ---------------------------------------------------------------------------
// math helpers
// ---------------------------------------------------------------------------
__device__ __forceinline__ float tanh_hw(float x) {          // MUFU.TANH
    float r;
    asm("tanh.approx.f32 %0, %1;" : "=f"(r) : "f"(x));
    return r;
}
__device__ __forceinline__ float rcp_fast(float x) {         // MUFU.RCP
    float r;
    asm("rcp.approx.f32 %0, %1;" : "=f"(r) : "f"(x));
    return r;
}
__device__ __forceinline__ float ex2_fast(float x) {         // MUFU.EX2
    float r;
    asm("ex2.approx.f32 %0, %1;" : "=f"(r) : "f"(x));
    return r;
}
// precise tanh via exp2: tanh(x) = 1 - 2/(1 + e^{2x}); |x| <= ~2.8 here.
__device__ __forceinline__ float tanh_exp(float x) {
    float e = ex2_fast(x * 2.8853900817779268f);  // 2*log2(e)
    float r = rcp_fast(e + 1.0f);
    return fmaf(-2.0f, r, 1.0f);
}

// f32x2 packed helpers (Blackwell)
typedef unsigned long long u64;
__device__ __forceinline__ u64 pk2(float lo, float hi) {
    u64 r;
    asm("mov.b64 %0, {%1, %2};" : "=l"(r) : "f"(lo), "f"(hi));
    return r;
}
__device__ __forceinline__ void upk2(u64 v, float& lo, float& hi) {
    asm("mov.b64 {%0, %1}, %2;" : "=f"(lo), "=f"(hi) : "l"(v));
}
__device__ __forceinline__ u64 fma2(u64 a, u64 b, u64 c) {
    u64 d;
    asm("fma.rn.f32x2 %0, %1, %2, %3;" : "=l"(d) : "l"(a), "l"(b), "l"(c));
    return d;
}

// ---------------------------------------------------------------------------
// Kernel 1 v2: 1 warp per block, 128 rows per block. lane = (half<<4) | g.
// Lane owns rows {g+16i, i=0..7} x cols [half*8, half*8+8).
// x staged in 4 chunks of 32 cols; column swizzle col' = col ^ ((row&8)<<1)
// makes the vertical 16-row LDS.32 pattern conflict-free.
// ---------------------------------------------------------------------------
__global__ __launch_bounds__(32) void qlstm_gemm(
    const float* __restrict__ x,
    const float* __restrict__ W0, const float* __restrict__ b0, const float* __restrict__ q0,
    const float* __restrict__ W1, const float* __restrict__ b1, const float* __restrict__ q1,
    const float* __restrict__ W2, const float* __restrict__ b2, const float* __restrict__ q2,
    const float* __restrict__ W3, const float* __restrict__ b3, const float* __restrict__ q3)
{
    __shared__ __align__(16) float xs[128 * 36];   // 32-col chunk, stride 36
    __shared__ __align__(16) float ws[128 * 16];   // combined weights [j][g*4+k]
    __shared__ float bt[16];

    int lane = (int)threadIdx.x;
    int g    = lane & 15;            // row-group id
    int half = lane >> 4;            // col half
    int kb   = half * 8;
    int xoff = (g & 8) << 1;         // 0 or 16: column swizzle for this lane's rows

    // stage combined W + bias/theta
    for (int idx = lane; idx < 2048; idx += 32) {
        int j = idx >> 4, c = idx & 15, gg = c >> 2, k = c & 3;
        const float* W = (gg == 0) ? W0 : (gg == 1) ? W1 : (gg == 2) ? W2 : W3;
        ws[j * 16 + c] = W[j * 4 + k];
    }
    if (lane < 16) {
        int gg = lane >> 2, k = lane & 3;
        const float* bb = (gg == 0) ? b0 : (gg == 1) ? b1 : (gg == 2) ? b2 : b3;
        const float* qq = (gg == 0) ? q0 : (gg == 1) ? q1 : (gg == 2) ? q2 : q3;
        bt[lane] = bb[k] + qq[k];
    }

    size_t row0 = (size_t)blockIdx.x * 128;
    const float4* xin4 = (const float4*)x + row0 * 32;

    u64 acc[8][4];
    #pragma unroll
    for (int i = 0; i < 8; i++)
        #pragma unroll
        for (int p = 0; p < 4; p++)
            acc[i][p] = pk2(bt[kb + 2 * p], bt[kb + 2 * p + 1]);
    __syncwarp();

    #pragma unroll 1
    for (int c = 0; c < 4; c++) {
        // stage x chunk: 128 rows x 32 cols (swizzled)
        #pragma unroll 4
        for (int it = 0; it < 32; it++) {
            int idx = lane + it * 32;
            int row = idx >> 3, j4 = idx & 7;
            float4 v = xin4[(size_t)row * 32 + c * 8 + j4];
            int colw = (j4 * 4) ^ ((row & 8) << 1);
            *(float4*)&xs[row * 36 + colw] = v;
        }
        __syncwarp();

        #pragma unroll 4
        for (int jj = 0; jj < 32; jj++) {
            int j = c * 32 + jj;
            const ulonglong2* wp = (const ulonglong2*)&ws[j * 16 + kb];
            ulonglong2 wa = wp[0];
            ulonglong2 wb = wp[1];
            int colx = jj ^ xoff;
            #pragma unroll
            for (int i = 0; i < 8; i++) {
                float xv = xs[(g + 16 * i) * 36 + colx];
                u64 xp = pk2(xv, xv);
                acc[i][0] = fma2(xp, wa.x, acc[i][0]);
                acc[i][1] = fma2(xp, wa.y, acc[i][1]);
                acc[i][2] = fma2(xp, wb.x, acc[i][2]);
                acc[i][3] = fma2(xp, wb.y, acc[i][3]);
            }
        }
        __syncwarp();
    }

    // write out: 8 rows x 8 cols per lane
    #pragma unroll
    for (int i = 0; i < 8; i++) {
        float4 r0, r1;
        upk2(acc[i][0], r0.x, r0.y);
        upk2(acc[i][1], r0.z, r0.w);
        upk2(acc[i][2], r1.x, r1.y);
        upk2(acc[i][3], r1.z, r1.w);
        float4* dst = (float4*)&g_pre[(row0 + g + 16 * i) * 16 + kb];
        dst[0] = r0;
        dst[1] = r1;
    }
}

// ---------------------------------------------------------------------------
// One recurrence step (quad layout + butterfly transpose). Reads P (pre row),
// updates ck (lane-owned c), hown, and the broadcast h0..h3.
// ---------------------------------------------------------------------------
#define QSTEP(P)                                                              \
    {                                                                         \
        u64 z01 = pk2((P).x, (P).y), z23 = pk2((P).z, (P).w);                 \
        u64 hp;                                                               \
        hp = pk2(h0, h0); z01 = fma2(hp, wh2[0][0], z01); z23 = fma2(hp, wh2[0][1], z23); \
        hp = pk2(h1, h1); z01 = fma2(hp, wh2[1][0], z01); z23 = fma2(hp, wh2[1][1], z23); \
        hp = pk2(h2, h2); z01 = fma2(hp, wh2[2][0], z01); z23 = fma2(hp, wh2[2][1], z23); \
        hp = pk2(h3, h3); z01 = fma2(hp, wh2[3][0], z01); z23 = fma2(hp, wh2[3][1], z23); \
        float z0, z1, z2, z3;                                                 \
        upk2(z01, z0, z1);                                                    \
        upk2(z23, z2, z3);                                                    \
        float q0 = __cosf(z0);                                                \
        float q1 = __cosf(z1);                                                \
        float q2 = __cosf(z2);                                                \
        float q3 = __cosf(z3);                                                \
        float m  = q0 * q1;                                                   \
        float r0 = q0;                                                        \
        float r1 = m;                                                         \
        float r2 = m * q2;                                                    \
        float r3 = m * (q2 * q3);                                             \
        {                                                                     \
            float v1 = o1 ? r0 : r1;                                          \
            float u1 = o1 ? r2 : r3;                                          \
            float x1 = __shfl_xor_sync(FULL, v1, 1);                          \
            float y1 = __shfl_xor_sync(FULL, u1, 1);                          \
            r0 = o1 ? x1 : r0;  r1 = o1 ? r1 : x1;                            \
            r2 = o1 ? y1 : r2;  r3 = o1 ? r3 : y1;                            \
            float v2 = o2 ? r0 : r2;                                          \
            float u2 = o2 ? r1 : r3;                                          \
            float x2 = __shfl_xor_sync(FULL, v2, 2);                          \
            float y2 = __shfl_xor_sync(FULL, u2, 2);                          \
            r0 = o2 ? x2 : r0;  r1 = o2 ? y2 : r1;                            \
            r2 = o2 ? r2 : x2;  r3 = o2 ? r3 : y2;                            \
        }                                                                     \
        float f = fmaf(0.5f, tanh_hw(0.5f * r0), 0.5f);                       \
        float i = fmaf(0.5f, tanh_hw(0.5f * r1), 0.5f);                       \
        float u = tanh_hw(r2);                                                \
        float o = fmaf(0.5f, tanh_hw(0.5f * r3), 0.5f);                       \
        ck = fmaf(f, ck, i * u);                                              \
        hown = o * tanh_exp(ck);                                              \
        h0 = __shfl_sync(FULL, hown, base);                                   \
        h1 = __shfl_sync(FULL, hown, base + 1);                               \
        h2 = __shfl_sync(FULL, hown, base + 2);                               \
        h3 = __shfl_sync(FULL, hown, base + 3);                               \
    }

// ---------------------------------------------------------------------------
// Kernel 2: sequence-parallel scan. 256 blocks x 128 threads (4 warps/block).
// blockIdx.x = chunk*8 + elem_group. Serial wall = BURN + CHUNK = 192 steps.
// Chunks 0 and 1 are exact (burn clamped at t=0); chunks >=2 burn 128 steps
// (residual <= rho^128 ~ 1e-6 even at pessimistic rho=0.9).
// ---------------------------------------------------------------------------
__global__ __launch_bounds__(128) void qlstm_scan(
    const float* __restrict__ W0, const float* __restrict__ W1,
    const float* __restrict__ W2, const float* __restrict__ W3,
    float* __restrict__ out)
{
    const unsigned FULL = 0xffffffffu;
    int warp = (int)threadIdx.x >> 5;
    int lane = (int)threadIdx.x & 31;
    int g    = lane & 3;
    int base = lane & ~3;
    bool o1  = (g & 1) != 0;
    bool o2  = (g & 2) != 0;

    int ci = (int)blockIdx.x >> 3;          // chunk index 0..31
    int eg = (int)blockIdx.x & 7;           // element group 0..7
    int b  = eg * 32 + warp * 8 + (lane >> 2);

    int t0 = ci * CHUNK;
    int tb = t0 - BURN; if (tb < 0) tb = 0;
    int nburn = t0 - tb;                    // 0, 64, or 128 (multiple of 4)

    // recurrent weights for this lane's gate, packed f32x2
    const float* W = (g == 0) ? W0 : (g == 1) ? W1 : (g == 2) ? W2 : W3;
    u64 wh2[4][2];
    #pragma unroll
    for (int j = 0; j < 4; j++) {
        wh2[j][0] = pk2(W[(DD + j) * 4 + 0], W[(DD + j) * 4 + 1]);
        wh2[j][1] = pk2(W[(DD + j) * 4 + 2], W[(DD + j) * 4 + 3]);
    }

    float h0 = 0.f, h1 = 0.f, h2 = 0.f, h3 = 0.f;
    float ck = 0.f;
    float hown = 0.f;

    // 4-deep register prefetch ring over pre[t][b][g*4..g*4+3] (float4/t).
    const float4* pp = (const float4*)g_pre + (size_t)b * 4 + g + (size_t)tb * 1024;
    float4 buf[4];
    buf[0] = pp[0];
    buf[1] = pp[1024];
    buf[2] = pp[2048];
    buf[3] = pp[3072];
    pp += 4096;

    // burn-in: establish (h,c) without storing
    #pragma unroll 4
    for (int t = 0; t < nburn; t++) {
        float4 P = buf[t & 3];
        buf[t & 3] = *pp;
        pp += 1024;
        QSTEP(P)
    }

    // emit CHUNK steps
    float* op = out + (size_t)t0 * (BB * 4) + (size_t)b * 4 + g;
    #pragma unroll 4
    for (int t = 0; t < CHUNK; t++) {
        float4 P = buf[t & 3];
        buf[t & 3] = *pp;       // padded region covers the t0+CHUNK+3 tail
        pp += 1024;
        QSTEP(P)
        *op = hown;             // coalesced STG.32
        op += BB * 4;
    }

    // trailing hx / cx blocks: only the last chunk owns the final state
    if (ci == NCHUNK - 1) {
        out[(size_t)TT * BB * 4 + (size_t)b * 4 + g] = hown;
        out[(size_t)TT * BB * 4 + (size_t)BB * 4 + (size_t)b * 4 + g] = ck;
    }
}

// ---------------------------------------------------------------------------
extern "C" void kernel_launch(void* const* d_in, const int* in_sizes, int n_in,
                              void* d_out, int out_size) {
    const float* x  = (const float*)d_in[0];
    const float* Wf = (const float*)d_in[1];
    const float* bf = (const float*)d_in[2];
    const float* qf = (const float*)d_in[3];
    const float* Wi = (const float*)d_in[4];
    const float* bi = (const float*)d_in[5];
    const float* qi = (const float*)d_in[6];
    const float* Wu = (const float*)d_in[7];
    const float* bu = (const float*)d_in[8];
    const float* qu = (const float*)d_in[9];
    const float* Wo = (const float*)d_in[10];
    const float* bo = (const float*)d_in[11];
    const float* qo = (const float*)d_in[12];

    qlstm_gemm<<<ROWS / 128, 32>>>(x, Wf, bf, qf, Wi, bi, qi, Wu, bu, qu, Wo, bo, qo);
    qlstm_scan<<<NCHUNK * 8, 128>>>(Wf, Wi, Wu, Wo, (float*)d_out);
}

// round 14
// speedup vs baseline: 1.6996x; 1.6996x over previous
// QLSTM: quantum-gate LSTM, T=2048, B=256, D=128, H=NQ=4.
//
// Kernel 1 (qlstm_gemm) v3: ROW-OWNER layout. Each lane owns one full row
//   (16 outputs, 8 f32x2 accums). W is lane-uniform per k -> 4 broadcast
//   LDS.128 (conflict-free by definition); x staged per-warp with row
//   stride 33 floats -> scalar column LDS bank = (lane+k) mod 32, provably
//   conflict-free. LDG fully coalesced. fma2 floor 31us, LDG floor ~45us.
//
// Kernel 2 (qlstm_scan): UNCHANGED from the validated 54.9us version.
//   Sequence-parallel: CHUNK=64, BURN=128 (f=sigmoid(p), p in [-1,1] ->
//   contraction <=0.731/step; BURN=256 and BURN=128 both bit-exact).
//   Serial wall = 192 steps; quad layout + butterfly transpose, 4-deep
//   register prefetch ring, MUFU.TANH gates, ex2+rcp tanh(c).

#include <cuda_runtime.h>
#include <cstdint>

#define TT 2048
#define BB 256
#define DD 128
#define ROWS (TT * BB)   // 524288
#define CHUNK 64
#define NCHUNK (TT / CHUNK)   // 32
#define BURN 128

// scratch: pre-activations [T][B][16] + 4 timesteps padding (ring overrun)
__device__ __align__(128) float g_pre[(TT + 4) * BB * 16];

// ---------------------------------------------------------------------------
// math helpers
// ---------------------------------------------------------------------------
__device__ __forceinline__ float tanh_hw(float x) {          // MUFU.TANH
    float r;
    asm("tanh.approx.f32 %0, %1;" : "=f"(r) : "f"(x));
    return r;
}
__device__ __forceinline__ float rcp_fast(float x) {         // MUFU.RCP
    float r;
    asm("rcp.approx.f32 %0, %1;" : "=f"(r) : "f"(x));
    return r;
}
__device__ __forceinline__ float ex2_fast(float x) {         // MUFU.EX2
    float r;
    asm("ex2.approx.f32 %0, %1;" : "=f"(r) : "f"(x));
    return r;
}
// precise tanh via exp2: tanh(x) = 1 - 2/(1 + e^{2x}); |x| <= ~2.8 here.
__device__ __forceinline__ float tanh_exp(float x) {
    float e = ex2_fast(x * 2.8853900817779268f);  // 2*log2(e)
    float r = rcp_fast(e + 1.0f);
    return fmaf(-2.0f, r, 1.0f);
}

// f32x2 packed helpers (Blackwell)
typedef unsigned long long u64;
__device__ __forceinline__ u64 pk2(float lo, float hi) {
    u64 r;
    asm("mov.b64 %0, {%1, %2};" : "=l"(r) : "f"(lo), "f"(hi));
    return r;
}
__device__ __forceinline__ void upk2(u64 v, float& lo, float& hi) {
    asm("mov.b64 {%0, %1}, %2;" : "=f"(lo), "=f"(hi) : "l"(v));
}
__device__ __forceinline__ u64 fma2(u64 a, u64 b, u64 c) {
    u64 d;
    asm("fma.rn.f32x2 %0, %1, %2, %3;" : "=l"(d) : "l"(a), "l"(b), "l"(c));
    return d;
}

// ---------------------------------------------------------------------------
// Kernel 1 v3: 128 threads/block, 128 rows/block (32 rows per warp, lane owns
// one row). x staged per-warp in 4 k-chunks of 32 cols, row stride 33 floats.
// ---------------------------------------------------------------------------
__global__ __launch_bounds__(128) void qlstm_gemm(
    const float* __restrict__ x,
    const float* __restrict__ W0, const float* __restrict__ b0, const float* __restrict__ q0,
    const float* __restrict__ W1, const float* __restrict__ b1, const float* __restrict__ q1,
    const float* __restrict__ W2, const float* __restrict__ b2, const float* __restrict__ q2,
    const float* __restrict__ W3, const float* __restrict__ b3, const float* __restrict__ q3)
{
    __shared__ __align__(16) float ws[128 * 16];     // combined W [k][g*4+q]
    __shared__ __align__(16) float xs[4 * 32 * 33];  // per-warp x tile, stride 33
    __shared__ float bt[16];

    int tid  = (int)threadIdx.x;
    int warp = tid >> 5;
    int lane = tid & 31;

    // stage combined W + bias/theta (once per block)
    for (int idx = tid; idx < 2048; idx += 128) {
        int j = idx >> 4, c = idx & 15, gg = c >> 2, k = c & 3;
        const float* W = (gg == 0) ? W0 : (gg == 1) ? W1 : (gg == 2) ? W2 : W3;
        ws[j * 16 + c] = W[j * 4 + k];
    }
    if (tid < 16) {
        int gg = tid >> 2, k = tid & 3;
        const float* bb = (gg == 0) ? b0 : (gg == 1) ? b1 : (gg == 2) ? b2 : b3;
        const float* qq = (gg == 0) ? q0 : (gg == 1) ? q1 : (gg == 2) ? q2 : q3;
        bt[tid] = bb[k] + qq[k];
    }
    __syncthreads();

    size_t row0 = (size_t)blockIdx.x * 128 + warp * 32;   // warp's first row
    const float4* xin4 = (const float4*)x + row0 * 32;    // row stride 32 float4
    float* xw = &xs[warp * (32 * 33)];

    u64 acc[8];
    #pragma unroll
    for (int p = 0; p < 8; p++)
        acc[p] = pk2(bt[2 * p], bt[2 * p + 1]);

    #pragma unroll 1
    for (int c = 0; c < 4; c++) {
        __syncwarp();
        // stage 32 rows x 32 cols: LDG.128 coalesced (8 lanes per row line),
        // STS.32 x4 at stride-33 rows: bank (row + 4q + j) mod 32 -> all 32.
        #pragma unroll
        for (int it = 0; it < 8; it++) {
            int idx = lane + it * 32;
            int row = idx >> 3, q = idx & 7;
            float4 v = xin4[(size_t)row * 32 + c * 8 + q];
            float* d = &xw[row * 33 + q * 4];
            d[0] = v.x; d[1] = v.y; d[2] = v.z; d[3] = v.w;
        }
        __syncwarp();

        const float* xr = &xw[lane * 33];   // scalar reads: bank (lane+k)%32
        #pragma unroll 8
        for (int k = 0; k < 32; k++) {
            int kk = c * 32 + k;
            const ulonglong2* wp = (const ulonglong2*)&ws[kk * 16];
            ulonglong2 wa = wp[0];   // broadcast (lane-uniform address)
            ulonglong2 wb = wp[1];
            float xv = xr[k];
            u64 xp = pk2(xv, xv);
            acc[0] = fma2(xp, wa.x, acc[0]);
            acc[1] = fma2(xp, wa.y, acc[1]);
            acc[2] = fma2(xp, wb.x, acc[2]);
            acc[3] = fma2(xp, wb.y, acc[3]);
            ulonglong2 wc = wp[2];
            ulonglong2 wd = wp[3];
            acc[4] = fma2(xp, wc.x, acc[4]);
            acc[5] = fma2(xp, wc.y, acc[5]);
            acc[6] = fma2(xp, wd.x, acc[6]);
            acc[7] = fma2(xp, wd.y, acc[7]);
        }
    }

    // write: lane's row, 16 floats = 4 STG.128 (2KB contiguous per warp)
    float4 r0, r1, r2, r3;
    upk2(acc[0], r0.x, r0.y); upk2(acc[1], r0.z, r0.w);
    upk2(acc[2], r1.x, r1.y); upk2(acc[3], r1.z, r1.w);
    upk2(acc[4], r2.x, r2.y); upk2(acc[5], r2.z, r2.w);
    upk2(acc[6], r3.x, r3.y); upk2(acc[7], r3.z, r3.w);
    float4* dst = (float4*)&g_pre[(row0 + lane) * 16];
    dst[0] = r0; dst[1] = r1; dst[2] = r2; dst[3] = r3;
}

// ---------------------------------------------------------------------------
// One recurrence step (quad layout + butterfly transpose). Reads P (pre row),
// updates ck (lane-owned c), hown, and the broadcast h0..h3.
// ---------------------------------------------------------------------------
#define QSTEP(P)                                                              \
    {                                                                         \
        u64 z01 = pk2((P).x, (P).y), z23 = pk2((P).z, (P).w);                 \
        u64 hp;                                                               \
        hp = pk2(h0, h0); z01 = fma2(hp, wh2[0][0], z01); z23 = fma2(hp, wh2[0][1], z23); \
        hp = pk2(h1, h1); z01 = fma2(hp, wh2[1][0], z01); z23 = fma2(hp, wh2[1][1], z23); \
        hp = pk2(h2, h2); z01 = fma2(hp, wh2[2][0], z01); z23 = fma2(hp, wh2[2][1], z23); \
        hp = pk2(h3, h3); z01 = fma2(hp, wh2[3][0], z01); z23 = fma2(hp, wh2[3][1], z23); \
        float z0, z1, z2, z3;                                                 \
        upk2(z01, z0, z1);                                                    \
        upk2(z23, z2, z3);                                                    \
        float q0 = __cosf(z0);                                                \
        float q1 = __cosf(z1);                                                \
        float q2 = __cosf(z2);                                                \
        float q3 = __cosf(z3);                                                \
        float m  = q0 * q1;                                                   \
        float r0 = q0;                                                        \
        float r1 = m;                                                         \
        float r2 = m * q2;                                                    \
        float r3 = m * (q2 * q3);                                             \
        {                                                                     \
            float v1 = o1 ? r0 : r1;                                          \
            float u1 = o1 ? r2 : r3;                                          \
            float x1 = __shfl_xor_sync(FULL, v1, 1);                          \
            float y1 = __shfl_xor_sync(FULL, u1, 1);                          \
            r0 = o1 ? x1 : r0;  r1 = o1 ? r1 : x1;                            \
            r2 = o1 ? y1 : r2;  r3 = o1 ? r3 : y1;                            \
            float v2 = o2 ? r0 : r2;                                          \
            float u2 = o2 ? r1 : r3;                                          \
            float x2 = __shfl_xor_sync(FULL, v2, 2);                          \
            float y2 = __shfl_xor_sync(FULL, u2, 2);                          \
            r0 = o2 ? x2 : r0;  r1 = o2 ? y2 : r1;                            \
            r2 = o2 ? r2 : x2;  r3 = o2 ? r3 : y2;                            \
        }                                                                     \
        float f = fmaf(0.5f, tanh_hw(0.5f * r0), 0.5f);                       \
        float i = fmaf(0.5f, tanh_hw(0.5f * r1), 0.5f);                       \
        float u = tanh_hw(r2);                                                \
        float o = fmaf(0.5f, tanh_hw(0.5f * r3), 0.5f);                       \
        ck = fmaf(f, ck, i * u);                                              \
        hown = o * tanh_exp(ck);                                              \
        h0 = __shfl_sync(FULL, hown, base);                                   \
        h1 = __shfl_sync(FULL, hown, base + 1);                               \
        h2 = __shfl_sync(FULL, hown, base + 2);                               \
        h3 = __shfl_sync(FULL, hown, base + 3);                               \
    }

// ---------------------------------------------------------------------------
// Kernel 2: sequence-parallel scan (UNCHANGED, validated 54.9us).
// 256 blocks x 128 threads; blockIdx.x = chunk*8 + elem_group.
// ---------------------------------------------------------------------------
__global__ __launch_bounds__(128) void qlstm_scan(
    const float* __restrict__ W0, const float* __restrict__ W1,
    const float* __restrict__ W2, const float* __restrict__ W3,
    float* __restrict__ out)
{
    const unsigned FULL = 0xffffffffu;
    int warp = (int)threadIdx.x >> 5;
    int lane = (int)threadIdx.x & 31;
    int g    = lane & 3;
    int base = lane & ~3;
    bool o1  = (g & 1) != 0;
    bool o2  = (g & 2) != 0;

    int ci = (int)blockIdx.x >> 3;          // chunk index 0..31
    int eg = (int)blockIdx.x & 7;           // element group 0..7
    int b  = eg * 32 + warp * 8 + (lane >> 2);

    int t0 = ci * CHUNK;
    int tb = t0 - BURN; if (tb < 0) tb = 0;
    int nburn = t0 - tb;                    // 0, 64, or 128 (multiple of 4)

    // recurrent weights for this lane's gate, packed f32x2
    const float* W = (g == 0) ? W0 : (g == 1) ? W1 : (g == 2) ? W2 : W3;
    u64 wh2[4][2];
    #pragma unroll
    for (int j = 0; j < 4; j++) {
        wh2[j][0] = pk2(W[(DD + j) * 4 + 0], W[(DD + j) * 4 + 1]);
        wh2[j][1] = pk2(W[(DD + j) * 4 + 2], W[(DD + j) * 4 + 3]);
    }

    float h0 = 0.f, h1 = 0.f, h2 = 0.f, h3 = 0.f;
    float ck = 0.f;
    float hown = 0.f;

    // 4-deep register prefetch ring over pre[t][b][g*4..g*4+3] (float4/t).
    const float4* pp = (const float4*)g_pre + (size_t)b * 4 + g + (size_t)tb * 1024;
    float4 buf[4];
    buf[0] = pp[0];
    buf[1] = pp[1024];
    buf[2] = pp[2048];
    buf[3] = pp[3072];
    pp += 4096;

    // burn-in: establish (h,c) without storing
    #pragma unroll 4
    for (int t = 0; t < nburn; t++) {
        float4 P = buf[t & 3];
        buf[t & 3] = *pp;
        pp += 1024;
        QSTEP(P)
    }

    // emit CHUNK steps
    float* op = out + (size_t)t0 * (BB * 4) + (size_t)b * 4 + g;
    #pragma unroll 4
    for (int t = 0; t < CHUNK; t++) {
        float4 P = buf[t & 3];
        buf[t & 3] = *pp;       // padded region covers the t0+CHUNK+3 tail
        pp += 1024;
        QSTEP(P)
        *op = hown;             // coalesced STG.32
        op += BB * 4;
    }

    // trailing hx / cx blocks: only the last chunk owns the final state
    if (ci == NCHUNK - 1) {
        out[(size_t)TT * BB * 4 + (size_t)b * 4 + g] = hown;
        out[(size_t)TT * BB * 4 + (size_t)BB * 4 + (size_t)b * 4 + g] = ck;
    }
}

// ---------------------------------------------------------------------------
extern "C" void kernel_launch(void* const* d_in, const int* in_sizes, int n_in,
                              void* d_out, int out_size) {
    const float* x  = (const float*)d_in[0];
    const float* Wf = (const float*)d_in[1];
    const float* bf = (const float*)d_in[2];
    const float* qf = (const float*)d_in[3];
    const float* Wi = (const float*)d_in[4];
    const float* bi = (const float*)d_in[5];
    const float* qi = (const float*)d_in[6];
    const float* Wu = (const float*)d_in[7];
    const float* bu = (const float*)d_in[8];
    const float* qu = (const float*)d_in[9];
    const float* Wo = (const float*)d_in[10];
    const float* bo = (const float*)d_in[11];
    const float* qo = (const float*)d_in[12];

    qlstm_gemm<<<ROWS / 128, 128>>>(x, Wf, bf, qf, Wi, bi, qi, Wu, bu, qu, Wo, bo, qo);
    qlstm_scan<<<NCHUNK * 8, 128>>>(Wf, Wi, Wu, Wo, (float*)d_out);
}

// round 15
// speedup vs baseline: 1.9534x; 1.1493x over previous
// QLSTM: quantum-gate LSTM, T=2048, B=256, D=128, H=NQ=4.
//
// Kernel 1 (qlstm_gemm) v4: row-owner, broadcast-W, 2 ROWS PER LANE.
//   Lane owns rows {lane, lane+32} of its warp's 64-row tile; the 4
//   broadcast LDS.128 (W) per k are amortized over both rows:
//   (4 W + 2 x + 16 fma2)/2 = 11 instr/row/k vs 13 in v3. x staged
//   per-warp at row stride 33 -> scalar read bank (lane+k) mod 32,
//   conflict-free for both row sets (offset 32 = 0 mod 32).
//
// Kernel 2 (qlstm_scan): sequence-parallel, CHUNK=32, BURN=96.
//   f = sigmoid(p), p in [-1,1] -> contraction <= 0.731/step. BURN=128
//   was bit-exact (residual <~1e-7) => rho^96 <~ 6e-6. Serial wall =
//   96+32 = 128 steps. Per-step: quad layout + butterfly transpose,
//   4-deep register prefetch ring, MUFU.TANH gates, ex2+rcp tanh(c).

#include <cuda_runtime.h>
#include <cstdint>

#define TT 2048
#define BB 256
#define DD 128
#define ROWS (TT * BB)   // 524288
#define CHUNK 32
#define NCHUNK (TT / CHUNK)   // 64
#define BURN 96

// scratch: pre-activations [T][B][16] + 4 timesteps padding (ring overrun)
__device__ __align__(128) float g_pre[(TT + 4) * BB * 16];

// ---------------------------------------------------------------------------
// math helpers
// ---------------------------------------------------------------------------
__device__ __forceinline__ float tanh_hw(float x) {          // MUFU.TANH
    float r;
    asm("tanh.approx.f32 %0, %1;" : "=f"(r) : "f"(x));
    return r;
}
__device__ __forceinline__ float rcp_fast(float x) {         // MUFU.RCP
    float r;
    asm("rcp.approx.f32 %0, %1;" : "=f"(r) : "f"(x));
    return r;
}
__device__ __forceinline__ float ex2_fast(float x) {         // MUFU.EX2
    float r;
    asm("ex2.approx.f32 %0, %1;" : "=f"(r) : "f"(x));
    return r;
}
// precise tanh via exp2: tanh(x) = 1 - 2/(1 + e^{2x}); |x| <= ~2.8 here.
__device__ __forceinline__ float tanh_exp(float x) {
    float e = ex2_fast(x * 2.8853900817779268f);  // 2*log2(e)
    float r = rcp_fast(e + 1.0f);
    return fmaf(-2.0f, r, 1.0f);
}

// f32x2 packed helpers (Blackwell)
typedef unsigned long long u64;
__device__ __forceinline__ u64 pk2(float lo, float hi) {
    u64 r;
    asm("mov.b64 %0, {%1, %2};" : "=l"(r) : "f"(lo), "f"(hi));
    return r;
}
__device__ __forceinline__ void upk2(u64 v, float& lo, float& hi) {
    asm("mov.b64 {%0, %1}, %2;" : "=f"(lo), "=f"(hi) : "l"(v));
}
__device__ __forceinline__ u64 fma2(u64 a, u64 b, u64 c) {
    u64 d;
    asm("fma.rn.f32x2 %0, %1, %2, %3;" : "=l"(d) : "l"(a), "l"(b), "l"(c));
    return d;
}

// ---------------------------------------------------------------------------
// Kernel 1 v4: 128 threads/block, 256 rows/block (64 per warp, 2 per lane).
// ---------------------------------------------------------------------------
__global__ __launch_bounds__(128) void qlstm_gemm(
    const float* __restrict__ x,
    const float* __restrict__ W0, const float* __restrict__ b0, const float* __restrict__ q0,
    const float* __restrict__ W1, const float* __restrict__ b1, const float* __restrict__ q1,
    const float* __restrict__ W2, const float* __restrict__ b2, const float* __restrict__ q2,
    const float* __restrict__ W3, const float* __restrict__ b3, const float* __restrict__ q3)
{
    __shared__ __align__(16) float ws[128 * 16];      // combined W [k][g*4+q]
    __shared__ __align__(16) float xs[4 * 64 * 33];   // per-warp x tile
    __shared__ float bt[16];

    int tid  = (int)threadIdx.x;
    int warp = tid >> 5;
    int lane = tid & 31;

    // stage combined W + bias/theta (once per block)
    for (int idx = tid; idx < 2048; idx += 128) {
        int j = idx >> 4, c = idx & 15, gg = c >> 2, k = c & 3;
        const float* W = (gg == 0) ? W0 : (gg == 1) ? W1 : (gg == 2) ? W2 : W3;
        ws[j * 16 + c] = W[j * 4 + k];
    }
    if (tid < 16) {
        int gg = tid >> 2, k = tid & 3;
        const float* bb = (gg == 0) ? b0 : (gg == 1) ? b1 : (gg == 2) ? b2 : b3;
        const float* qq = (gg == 0) ? q0 : (gg == 1) ? q1 : (gg == 2) ? q2 : q3;
        bt[tid] = bb[k] + qq[k];
    }
    __syncthreads();

    size_t rowW = (size_t)blockIdx.x * 256 + warp * 64;   // warp's first row
    const float4* xin4 = (const float4*)x + rowW * 32;    // row stride 32 float4
    float* xw = &xs[warp * (64 * 33)];

    u64 acc0[8], acc1[8];
    #pragma unroll
    for (int p = 0; p < 8; p++) {
        u64 v = pk2(bt[2 * p], bt[2 * p + 1]);
        acc0[p] = v;
        acc1[p] = v;
    }

    #pragma unroll 1
    for (int c = 0; c < 4; c++) {
        __syncwarp();
        // stage 64 rows x 32 cols: LDG.128 coalesced; STS.32 banks
        // (row + 4q + j) mod 32 all-distinct per instruction.
        #pragma unroll
        for (int it = 0; it < 16; it++) {
            int idx = lane + it * 32;
            int row = idx >> 3, q = idx & 7;
            float4 v = xin4[(size_t)row * 32 + c * 8 + q];
            float* d = &xw[row * 33 + q * 4];
            d[0] = v.x; d[1] = v.y; d[2] = v.z; d[3] = v.w;
        }
        __syncwarp();

        const float* xr0 = &xw[lane * 33];          // bank (lane+k)%32
        const float* xr1 = &xw[(lane + 32) * 33];   // same banks (32 = 0 mod 32)
        #pragma unroll 8
        for (int k = 0; k < 32; k++) {
            int kk = c * 32 + k;
            const ulonglong2* wp = (const ulonglong2*)&ws[kk * 16];
            ulonglong2 wa = wp[0];   // broadcast (lane-uniform address)
            ulonglong2 wb = wp[1];
            ulonglong2 wc = wp[2];
            ulonglong2 wd = wp[3];
            float xv0 = xr0[k];
            float xv1 = xr1[k];
            u64 xp0 = pk2(xv0, xv0);
            u64 xp1 = pk2(xv1, xv1);
            acc0[0] = fma2(xp0, wa.x, acc0[0]);
            acc1[0] = fma2(xp1, wa.x, acc1[0]);
            acc0[1] = fma2(xp0, wa.y, acc0[1]);
            acc1[1] = fma2(xp1, wa.y, acc1[1]);
            acc0[2] = fma2(xp0, wb.x, acc0[2]);
            acc1[2] = fma2(xp1, wb.x, acc1[2]);
            acc0[3] = fma2(xp0, wb.y, acc0[3]);
            acc1[3] = fma2(xp1, wb.y, acc1[3]);
            acc0[4] = fma2(xp0, wc.x, acc0[4]);
            acc1[4] = fma2(xp1, wc.x, acc1[4]);
            acc0[5] = fma2(xp0, wc.y, acc0[5]);
            acc1[5] = fma2(xp1, wc.y, acc1[5]);
            acc0[6] = fma2(xp0, wd.x, acc0[6]);
            acc1[6] = fma2(xp1, wd.x, acc1[6]);
            acc0[7] = fma2(xp0, wd.y, acc0[7]);
            acc1[7] = fma2(xp1, wd.y, acc1[7]);
        }
    }

    // write both rows: 4 STG.128 each, warp-contiguous
    {
        float4 r0, r1, r2, r3;
        upk2(acc0[0], r0.x, r0.y); upk2(acc0[1], r0.z, r0.w);
        upk2(acc0[2], r1.x, r1.y); upk2(acc0[3], r1.z, r1.w);
        upk2(acc0[4], r2.x, r2.y); upk2(acc0[5], r2.z, r2.w);
        upk2(acc0[6], r3.x, r3.y); upk2(acc0[7], r3.z, r3.w);
        float4* dst = (float4*)&g_pre[(rowW + lane) * 16];
        dst[0] = r0; dst[1] = r1; dst[2] = r2; dst[3] = r3;
    }
    {
        float4 r0, r1, r2, r3;
        upk2(acc1[0], r0.x, r0.y); upk2(acc1[1], r0.z, r0.w);
        upk2(acc1[2], r1.x, r1.y); upk2(acc1[3], r1.z, r1.w);
        upk2(acc1[4], r2.x, r2.y); upk2(acc1[5], r2.z, r2.w);
        upk2(acc1[6], r3.x, r3.y); upk2(acc1[7], r3.z, r3.w);
        float4* dst = (float4*)&g_pre[(rowW + lane + 32) * 16];
        dst[0] = r0; dst[1] = r1; dst[2] = r2; dst[3] = r3;
    }
}

// ---------------------------------------------------------------------------
// One recurrence step (quad layout + butterfly transpose). Reads P (pre row),
// updates ck (lane-owned c), hown, and the broadcast h0..h3.
// ---------------------------------------------------------------------------
#define QSTEP(P)                                                              \
    {                                                                         \
        u64 z01 = pk2((P).x, (P).y), z23 = pk2((P).z, (P).w);                 \
        u64 hp;                                                               \
        hp = pk2(h0, h0); z01 = fma2(hp, wh2[0][0], z01); z23 = fma2(hp, wh2[0][1], z23); \
        hp = pk2(h1, h1); z01 = fma2(hp, wh2[1][0], z01); z23 = fma2(hp, wh2[1][1], z23); \
        hp = pk2(h2, h2); z01 = fma2(hp, wh2[2][0], z01); z23 = fma2(hp, wh2[2][1], z23); \
        hp = pk2(h3, h3); z01 = fma2(hp, wh2[3][0], z01); z23 = fma2(hp, wh2[3][1], z23); \
        float z0, z1, z2, z3;                                                 \
        upk2(z01, z0, z1);                                                    \
        upk2(z23, z2, z3);                                                    \
        float q0 = __cosf(z0);                                                \
        float q1 = __cosf(z1);                                                \
        float q2 = __cosf(z2);                                                \
        float q3 = __cosf(z3);                                                \
        float m  = q0 * q1;                                                   \
        float r0 = q0;                                                        \
        float r1 = m;                                                         \
        float r2 = m * q2;                                                    \
        float r3 = m * (q2 * q3);                                             \
        {                                                                     \
            float v1 = o1 ? r0 : r1;                                          \
            float u1 = o1 ? r2 : r3;                                          \
            float x1 = __shfl_xor_sync(FULL, v1, 1);                          \
            float y1 = __shfl_xor_sync(FULL, u1, 1);                          \
            r0 = o1 ? x1 : r0;  r1 = o1 ? r1 : x1;                            \
            r2 = o1 ? y1 : r2;  r3 = o1 ? r3 : y1;                            \
            float v2 = o2 ? r0 : r2;                                          \
            float u2 = o2 ? r1 : r3;                                          \
            float x2 = __shfl_xor_sync(FULL, v2, 2);                          \
            float y2 = __shfl_xor_sync(FULL, u2, 2);                          \
            r0 = o2 ? x2 : r0;  r1 = o2 ? y2 : r1;                            \
            r2 = o2 ? r2 : x2;  r3 = o2 ? r3 : y2;                            \
        }                                                                     \
        float f = fmaf(0.5f, tanh_hw(0.5f * r0), 0.5f);                       \
        float i = fmaf(0.5f, tanh_hw(0.5f * r1), 0.5f);                       \
        float u = tanh_hw(r2);                                                \
        float o = fmaf(0.5f, tanh_hw(0.5f * r3), 0.5f);                       \
        ck = fmaf(f, ck, i * u);                                              \
        hown = o * tanh_exp(ck);                                              \
        h0 = __shfl_sync(FULL, hown, base);                                   \
        h1 = __shfl_sync(FULL, hown, base + 1);                               \
        h2 = __shfl_sync(FULL, hown, base + 2);                               \
        h3 = __shfl_sync(FULL, hown, base + 3);                               \
    }

// ---------------------------------------------------------------------------
// Kernel 2: sequence-parallel scan. 512 blocks x 128 threads.
// blockIdx.x = chunk*8 + elem_group. Serial wall = 128 steps.
// Chunks with t0 <= 96 are exact; t0 >= 128 burn 96 steps.
// ---------------------------------------------------------------------------
__global__ __launch_bounds__(128) void qlstm_scan(
    const float* __restrict__ W0, const float* __restrict__ W1,
    const float* __restrict__ W2, const float* __restrict__ W3,
    float* __restrict__ out)
{
    const unsigned FULL = 0xffffffffu;
    int warp = (int)threadIdx.x >> 5;
    int lane = (int)threadIdx.x & 31;
    int g    = lane & 3;
    int base = lane & ~3;
    bool o1  = (g & 1) != 0;
    bool o2  = (g & 2) != 0;

    int ci = (int)blockIdx.x >> 3;          // chunk index 0..63
    int eg = (int)blockIdx.x & 7;           // element group 0..7
    int b  = eg * 32 + warp * 8 + (lane >> 2);

    int t0 = ci * CHUNK;
    int tb = t0 - BURN; if (tb < 0) tb = 0;
    int nburn = t0 - tb;                    // 0,32,64,96 (multiple of 4)

    // recurrent weights for this lane's gate, packed f32x2
    const float* W = (g == 0) ? W0 : (g == 1) ? W1 : (g == 2) ? W2 : W3;
    u64 wh2[4][2];
    #pragma unroll
    for (int j = 0; j < 4; j++) {
        wh2[j][0] = pk2(W[(DD + j) * 4 + 0], W[(DD + j) * 4 + 1]);
        wh2[j][1] = pk2(W[(DD + j) * 4 + 2], W[(DD + j) * 4 + 3]);
    }

    float h0 = 0.f, h1 = 0.f, h2 = 0.f, h3 = 0.f;
    float ck = 0.f;
    float hown = 0.f;

    // 4-deep register prefetch ring over pre[t][b][g*4..g*4+3] (float4/t).
    const float4* pp = (const float4*)g_pre + (size_t)b * 4 + g + (size_t)tb * 1024;
    float4 buf[4];
    buf[0] = pp[0];
    buf[1] = pp[1024];
    buf[2] = pp[2048];
    buf[3] = pp[3072];
    pp += 4096;

    // burn-in: establish (h,c) without storing
    #pragma unroll 4
    for (int t = 0; t < nburn; t++) {
        float4 P = buf[t & 3];
        buf[t & 3] = *pp;
        pp += 1024;
        QSTEP(P)
    }

    // emit CHUNK steps
    float* op = out + (size_t)t0 * (BB * 4) + (size_t)b * 4 + g;
    #pragma unroll 4
    for (int t = 0; t < CHUNK; t++) {
        float4 P = buf[t & 3];
        buf[t & 3] = *pp;       // padded region covers the t0+CHUNK+3 tail
        pp += 1024;
        QSTEP(P)
        *op = hown;             // coalesced STG.32
        op += BB * 4;
    }

    // trailing hx / cx blocks: only the last chunk owns the final state
    if (ci == NCHUNK - 1) {
        out[(size_t)TT * BB * 4 + (size_t)b * 4 + g] = hown;
        out[(size_t)TT * BB * 4 + (size_t)BB * 4 + (size_t)b * 4 + g] = ck;
    }
}

// ---------------------------------------------------------------------------
extern "C" void kernel_launch(void* const* d_in, const int* in_sizes, int n_in,
                              void* d_out, int out_size) {
    const float* x  = (const float*)d_in[0];
    const float* Wf = (const float*)d_in[1];
    const float* bf = (const float*)d_in[2];
    const float* qf = (const float*)d_in[3];
    const float* Wi = (const float*)d_in[4];
    const float* bi = (const float*)d_in[5];
    const float* qi = (const float*)d_in[6];
    const float* Wu = (const float*)d_in[7];
    const float* bu = (const float*)d_in[8];
    const float* qu = (const float*)d_in[9];
    const float* Wo = (const float*)d_in[10];
    const float* bo = (const float*)d_in[11];
    const float* qo = (const float*)d_in[12];

    qlstm_gemm<<<ROWS / 256, 128>>>(x, Wf, bf, qf, Wi, bi, qi, Wu, bu, qu, Wo, bo, qo);
    qlstm_scan<<<NCHUNK * 8, 128>>>(Wf, Wi, Wu, Wo, (float*)d_out);
}